// round 7
// baseline (speedup 1.0000x reference)
#include <cuda_runtime.h>

typedef unsigned long long ull;

#define T_STEPS  512
#define BATCH    64
#define EDIM     300
#define HDIM     512
#define NBLK     128
#define NTHREADS 256

// -------------------- persistent device scratch (no allocations) -----------
__device__ float g_h1[(size_t)T_STEPS * BATCH * HDIM];   // layer-0 hidden states, all t
__device__ float g_h2[2 * BATCH * HDIM];                 // layer-1 ping-pong
__device__ float g_zero[BATCH * HDIM];                   // never written: stays 0
__device__ float g_pooled[T_STEPS * HDIM];               // mean over batch of h2
__device__ unsigned g_count0, g_sense0, g_count1, g_sense1;

// -------------------- helpers ---------------------------------------------
__device__ __forceinline__ void fma2(ull& acc, ull a, ull b) {
    // packed 2x fp32 FMA (sm_100+): doubles fp32 MAC throughput per issue
    asm volatile("fma.rn.f32x2 %0, %1, %2, %0;" : "+l"(acc) : "l"(a), "l"(b));
}
__device__ __forceinline__ float hsum2(ull v) {
    return __uint_as_float((unsigned)v) + __uint_as_float((unsigned)(v >> 32));
}
__device__ __forceinline__ float sigf(float x) { return 1.0f / (1.0f + expf(-x)); }

// sense-reversing software grid barrier (grid <= 148 CTAs, always co-resident)
__device__ __forceinline__ void grid_bar(unsigned* cnt, unsigned* sense, unsigned& local_sense) {
    __syncthreads();
    if (threadIdx.x == 0) {
        unsigned target = local_sense + 1;
        local_sense = target;
        __threadfence();
        if (atomicAdd(cnt, 1) == gridDim.x - 1) {
            *cnt = 0;
            __threadfence();
            atomicExch(sense, target);          // release
        } else {
            while (atomicAdd(sense, 0) != target) { }
        }
        __threadfence();                        // acquire
    }
    __syncthreads();
}

// one 64-wide K-chunk of MACs: 3 gate rows, f32x2 packed
__device__ __forceinline__ void chunk_mac(const ulonglong2* __restrict__ hrow,
                                          const ulonglong2* __restrict__ wr,
                                          const ulonglong2* __restrict__ wz,
                                          const ulonglong2* __restrict__ wn,
                                          ull& r0, ull& r1, ull& z0, ull& z1,
                                          ull& n0, ull& n1) {
#pragma unroll
    for (int q = 0; q < 16; q++) {
        ulonglong2 hv = hrow[q];
        ulonglong2 wv = wr[q];
        fma2(r0, hv.x, wv.x); fma2(r1, hv.y, wv.y);
        wv = wz[q];
        fma2(z0, hv.x, wv.x); fma2(z1, hv.y, wv.y);
        wv = wn[q];
        fma2(n0, hv.x, wv.x); fma2(n1, hv.y, wv.y);
    }
}

// =====================  layer 0: embedding-gather + GRU  ====================
// CTA bk owns hidden units j0..j0+3. Weights resident in SMEM for all 512 steps.
// smem float4 layout: wih 12x81 (300->324 pad) | whh 12x129 (512->516 pad) | tile 64x17
__global__ void __launch_bounds__(NTHREADS, 1)
layer0_kernel(const int* __restrict__ texts, const float* __restrict__ emb,
              const float* __restrict__ Wih, const float* __restrict__ Whh,
              const float* __restrict__ bih, const float* __restrict__ bhh)
{
    extern __shared__ float4 smem[];
    float4* wih4  = smem;                      // 972 float4
    float4* whh4  = smem + 12 * 81;            // 1548 float4
    float4* tile4 = smem + 12 * 81 + 12 * 129; // 1088 float4

    const int tid = threadIdx.x;
    const int j0  = blockIdx.x * 4;
    const int b   = tid >> 2;
    const int jj  = tid & 3;
    const int j   = j0 + jj;

    unsigned local_sense = atomicAdd(&g_sense0, 0u);

    // stage input-projection weights (K=300 -> 75 float4, zero pad to 81)
    for (int idx = tid; idx < 12 * 81; idx += NTHREADS) {
        int m = idx / 81, f4 = idx - m * 81;
        int g = m >> 2, u = m & 3;
        float4 v = make_float4(0.f, 0.f, 0.f, 0.f);
        if (f4 < 75)
            v = reinterpret_cast<const float4*>(Wih + (size_t)(g * HDIM + j0 + u) * EDIM)[f4];
        wih4[idx] = v;
    }
    // stage recurrent weights (K=512 -> 128 float4, pad to 129)
    for (int idx = tid; idx < 12 * 129; idx += NTHREADS) {
        int m = idx / 129, f4 = idx - m * 129;
        int g = m >> 2, u = m & 3;
        float4 v = make_float4(0.f, 0.f, 0.f, 0.f);
        if (f4 < 128)
            v = reinterpret_cast<const float4*>(Whh + (size_t)(g * HDIM + j0 + u) * HDIM)[f4];
        whh4[idx] = v;
    }

    const float br  = bih[j] + bhh[j];
    const float bz  = bih[HDIM + j] + bhh[HDIM + j];
    const float bxn = bih[2 * HDIM + j];     // bih_n: outside r product
    const float bhn = bhh[2 * HDIM + j];     // bhh_n: INSIDE r product (PyTorch GRU)

    const ulonglong2* tile2 = reinterpret_cast<const ulonglong2*>(tile4);
    const ulonglong2* wR = reinterpret_cast<const ulonglong2*>(wih4 + jj * 81);
    const ulonglong2* wZ = reinterpret_cast<const ulonglong2*>(wih4 + (4 + jj) * 81);
    const ulonglong2* wN = reinterpret_cast<const ulonglong2*>(wih4 + (8 + jj) * 81);
    const ulonglong2* vR = reinterpret_cast<const ulonglong2*>(whh4 + jj * 129);
    const ulonglong2* vZ = reinterpret_cast<const ulonglong2*>(whh4 + (4 + jj) * 129);
    const ulonglong2* vN = reinterpret_cast<const ulonglong2*>(whh4 + (8 + jj) * 129);
    const ulonglong2* hrow = tile2 + b * 17;

    for (int t = 0; t < T_STEPS; t++) {
        const float* hprev = (t == 0) ? g_zero : (g_h1 + (size_t)(t - 1) * (BATCH * HDIM));
        const float4* hprev4 = reinterpret_cast<const float4*>(hprev);

        ull r0 = 0, r1 = 0, z0 = 0, z1 = 0, nx0 = 0, nx1 = 0, nh0 = 0, nh1 = 0;

        // ---- input-projection phase: gathered embedding, 5 chunks of 64 K ----
        for (int c = 0; c < 5; c++) {
            __syncthreads();
            for (int idx = tid; idx < 1024; idx += NTHREADS) {
                int rr = idx >> 4, f4 = idx & 15;
                int gf4 = c * 16 + f4;                 // 300 floats = 75 float4 exactly
                float4 v = make_float4(0.f, 0.f, 0.f, 0.f);
                if (gf4 < 75) {
                    int tok = texts[t * BATCH + rr];
                    v = reinterpret_cast<const float4*>(emb + (size_t)tok * EDIM)[gf4];
                }
                tile4[rr * 17 + f4] = v;
            }
            __syncthreads();
            chunk_mac(hrow, wR + c * 16, wZ + c * 16, wN + c * 16,
                      r0, r1, z0, z1, nx0, nx1);
        }
        // ---- recurrent phase: h[t-1], 8 chunks of 64 K ----
        for (int c = 0; c < 8; c++) {
            __syncthreads();
            for (int idx = tid; idx < 1024; idx += NTHREADS) {
                int rr = idx >> 4, f4 = idx & 15;
                tile4[rr * 17 + f4] = hprev4[rr * 128 + c * 16 + f4];
            }
            __syncthreads();
            chunk_mac(hrow, vR + c * 16, vZ + c * 16, vN + c * 16,
                      r0, r1, z0, z1, nh0, nh1);
        }

        float r = sigf(hsum2(r0) + hsum2(r1) + br);
        float z = sigf(hsum2(z0) + hsum2(z1) + bz);
        float n = tanhf(hsum2(nx0) + hsum2(nx1) + bxn +
                        r * (hsum2(nh0) + hsum2(nh1) + bhn));
        float hp   = hprev[b * HDIM + j];
        float hnew = (1.0f - z) * n + z * hp;
        g_h1[((size_t)t * BATCH + b) * HDIM + j] = hnew;

        grid_bar(&g_count0, &g_sense0, local_sense);
    }
}

// =====================  layer 1: GRU + batch-mean pooling  ==================
// smem float4 layout: wx 12x129 | wh 12x129 | tile 64x17
__global__ void __launch_bounds__(NTHREADS, 1)
layer1_kernel(const float* __restrict__ Wih, const float* __restrict__ Whh,
              const float* __restrict__ bih, const float* __restrict__ bhh)
{
    extern __shared__ float4 smem[];
    float4* wx4   = smem;               // 1548 float4
    float4* wh4   = smem + 12 * 129;    // 1548 float4
    float4* tile4 = smem + 24 * 129;    // 1088 float4
    __shared__ float hn_sh[NTHREADS];

    const int tid = threadIdx.x;
    const int j0  = blockIdx.x * 4;
    const int b   = tid >> 2;
    const int jj  = tid & 3;
    const int j   = j0 + jj;

    unsigned local_sense = atomicAdd(&g_sense1, 0u);

    for (int idx = tid; idx < 12 * 129; idx += NTHREADS) {
        int m = idx / 129, f4 = idx - m * 129;
        int g = m >> 2, u = m & 3;
        float4 v = make_float4(0.f, 0.f, 0.f, 0.f);
        if (f4 < 128)
            v = reinterpret_cast<const float4*>(Wih + (size_t)(g * HDIM + j0 + u) * HDIM)[f4];
        wx4[idx] = v;
    }
    for (int idx = tid; idx < 12 * 129; idx += NTHREADS) {
        int m = idx / 129, f4 = idx - m * 129;
        int g = m >> 2, u = m & 3;
        float4 v = make_float4(0.f, 0.f, 0.f, 0.f);
        if (f4 < 128)
            v = reinterpret_cast<const float4*>(Whh + (size_t)(g * HDIM + j0 + u) * HDIM)[f4];
        wh4[idx] = v;
    }

    const float br  = bih[j] + bhh[j];
    const float bz  = bih[HDIM + j] + bhh[HDIM + j];
    const float bxn = bih[2 * HDIM + j];
    const float bhn = bhh[2 * HDIM + j];

    const ulonglong2* tile2 = reinterpret_cast<const ulonglong2*>(tile4);
    const ulonglong2* wR = reinterpret_cast<const ulonglong2*>(wx4 + jj * 129);
    const ulonglong2* wZ = reinterpret_cast<const ulonglong2*>(wx4 + (4 + jj) * 129);
    const ulonglong2* wN = reinterpret_cast<const ulonglong2*>(wx4 + (8 + jj) * 129);
    const ulonglong2* vR = reinterpret_cast<const ulonglong2*>(wh4 + jj * 129);
    const ulonglong2* vZ = reinterpret_cast<const ulonglong2*>(wh4 + (4 + jj) * 129);
    const ulonglong2* vN = reinterpret_cast<const ulonglong2*>(wh4 + (8 + jj) * 129);
    const ulonglong2* hrow = tile2 + b * 17;

    for (int t = 0; t < T_STEPS; t++) {
        const float* xsrc  = g_h1 + (size_t)t * (BATCH * HDIM);
        const float* hprev = (t == 0) ? g_zero : (g_h2 + ((t - 1) & 1) * (BATCH * HDIM));
        const float4* xsrc4  = reinterpret_cast<const float4*>(xsrc);
        const float4* hprev4 = reinterpret_cast<const float4*>(hprev);

        ull r0 = 0, r1 = 0, z0 = 0, z1 = 0, nx0 = 0, nx1 = 0, nh0 = 0, nh1 = 0;

        // input projection from h1[t]
        for (int c = 0; c < 8; c++) {
            __syncthreads();
            for (int idx = tid; idx < 1024; idx += NTHREADS) {
                int rr = idx >> 4, f4 = idx & 15;
                tile4[rr * 17 + f4] = xsrc4[rr * 128 + c * 16 + f4];
            }
            __syncthreads();
            chunk_mac(hrow, wR + c * 16, wZ + c * 16, wN + c * 16,
                      r0, r1, z0, z1, nx0, nx1);
        }
        // recurrent from h2[t-1]
        for (int c = 0; c < 8; c++) {
            __syncthreads();
            for (int idx = tid; idx < 1024; idx += NTHREADS) {
                int rr = idx >> 4, f4 = idx & 15;
                tile4[rr * 17 + f4] = hprev4[rr * 128 + c * 16 + f4];
            }
            __syncthreads();
            chunk_mac(hrow, vR + c * 16, vZ + c * 16, vN + c * 16,
                      r0, r1, z0, z1, nh0, nh1);
        }

        float r = sigf(hsum2(r0) + hsum2(r1) + br);
        float z = sigf(hsum2(z0) + hsum2(z1) + bz);
        float n = tanhf(hsum2(nx0) + hsum2(nx1) + bxn +
                        r * (hsum2(nh0) + hsum2(nh1) + bhn));
        float hp   = hprev[b * HDIM + j];
        float hnew = (1.0f - z) * n + z * hp;
        g_h2[(t & 1) * (BATCH * HDIM) + b * HDIM + j] = hnew;

        // mean over batch for this step's owned units
        hn_sh[tid] = hnew;                 // tid = b*4 + jj
        __syncthreads();
        if (tid < 4) {
            float s = 0.f;
#pragma unroll
            for (int bb = 0; bb < BATCH; bb++) s += hn_sh[(bb << 2) + tid];
            g_pooled[t * HDIM + j0 + tid] = s * (1.0f / 64.0f);
        }

        grid_bar(&g_count1, &g_sense1, local_sense);
    }
}

// =====================  final FC: [T,H] @ [L,H]^T + b  ======================
__global__ void fc_kernel(const float* __restrict__ fcW, const float* __restrict__ fcb,
                          float* __restrict__ out)
{
    int t    = blockIdx.x;
    int l    = threadIdx.x >> 5;   // 5 warps -> 5 outputs
    int lane = threadIdx.x & 31;
    const float* p = g_pooled + t * HDIM;
    const float* w = fcW + l * HDIM;
    float s = 0.f;
#pragma unroll 4
    for (int k = lane; k < HDIM; k += 32) s += p[k] * w[k];
#pragma unroll
    for (int o = 16; o; o >>= 1) s += __shfl_xor_sync(0xffffffffu, s, o);
    if (lane == 0) out[t * 5 + l] = s + fcb[l];
}

// ===========================================================================
extern "C" void kernel_launch(void* const* d_in, const int* in_sizes, int n_in,
                              void* d_out, int out_size) {
    (void)in_sizes; (void)n_in; (void)out_size;
    const int*   texts = (const int*)  d_in[0];
    const float* emb   = (const float*)d_in[1];
    const float* Wih0  = (const float*)d_in[2];
    const float* Whh0  = (const float*)d_in[3];
    const float* bih0  = (const float*)d_in[4];
    const float* bhh0  = (const float*)d_in[5];
    const float* Wih1  = (const float*)d_in[6];
    const float* Whh1  = (const float*)d_in[7];
    const float* bih1  = (const float*)d_in[8];
    const float* bhh1  = (const float*)d_in[9];
    const float* fcW   = (const float*)d_in[10];
    const float* fcb   = (const float*)d_in[11];
    float* out = (float*)d_out;

    const int smem0 = (12 * 81 + 12 * 129 + 64 * 17) * 16;   // 57,728 B
    const int smem1 = (24 * 129 + 64 * 17) * 16;             // 66,944 B
    cudaFuncSetAttribute(layer0_kernel, cudaFuncAttributeMaxDynamicSharedMemorySize, smem0);
    cudaFuncSetAttribute(layer1_kernel, cudaFuncAttributeMaxDynamicSharedMemorySize, smem1);

    layer0_kernel<<<NBLK, NTHREADS, smem0>>>(texts, emb, Wih0, Whh0, bih0, bhh0);
    layer1_kernel<<<NBLK, NTHREADS, smem1>>>(Wih1, Whh1, bih1, bhh1);
    fc_kernel<<<T_STEPS, 160>>>(fcW, fcb, out);
}

// round 8
// speedup vs baseline: 2.2429x; 2.2429x over previous
#include <cuda_runtime.h>

typedef unsigned long long ull;

#define T_STEPS  512
#define BATCH    64
#define EDIM     300
#define HDIM     512
#define BH       (BATCH * HDIM)
#define NBLK     128
#define NTHREADS 256

// -------------------- persistent device scratch (no allocations) -----------
__device__ float g_h1[(size_t)T_STEPS * BH];   // layer-0 hidden, all t (64 MB)
__device__ float g_h2[(size_t)T_STEPS * BH];   // layer-1 hidden, all t (64 MB) — full
                                               // history: every slice read exactly once,
                                               // so no stale-L1 hazard
__device__ float g_zero[BH];                   // never written: stays 0
__device__ float g_pooled[T_STEPS * HDIM];     // mean over batch of h2
__device__ unsigned g_count, g_sense;

// -------------------- helpers ---------------------------------------------
__device__ __forceinline__ void fma2(ull& acc, ull a, ull b) {
    asm volatile("fma.rn.f32x2 %0, %1, %2, %0;" : "+l"(acc) : "l"(a), "l"(b));
}
__device__ __forceinline__ float hsum2(ull v) {
    return __uint_as_float((unsigned)v) + __uint_as_float((unsigned)(v >> 32));
}
__device__ __forceinline__ float sigf(float x) { return 1.0f / (1.0f + expf(-x)); }

// Grid barrier: atomic arrive, VOLATILE-LOAD poll (reads don't serialize the
// LTS atomic ALU the way atomicAdd-polling does).
__device__ __forceinline__ void grid_bar(unsigned& ls) {
    __syncthreads();
    if (threadIdx.x == 0) {
        unsigned target = ++ls;
        __threadfence();                              // release our stores
        if (atomicAdd(&g_count, 1) == gridDim.x - 1) {
            g_count = 0;
            __threadfence();
            *(volatile unsigned*)&g_sense = target;   // release
        } else {
            while (*(volatile unsigned*)&g_sense != target) { }
        }
        __threadfence();                              // acquire
    }
    __syncthreads();
}

// one 64-wide K-chunk of MACs: 3 gate rows (one layer)
__device__ __forceinline__ void mac6(const ulonglong2* __restrict__ hrow,
                                     const ulonglong2* __restrict__ wr,
                                     const ulonglong2* __restrict__ wz,
                                     const ulonglong2* __restrict__ wn,
                                     ull& r0, ull& r1, ull& z0, ull& z1,
                                     ull& n0, ull& n1) {
#pragma unroll
    for (int q = 0; q < 16; q++) {
        ulonglong2 hv = hrow[q];
        ulonglong2 w  = wr[q];
        fma2(r0, hv.x, w.x); fma2(r1, hv.y, w.y);
        w = wz[q];
        fma2(z0, hv.x, w.x); fma2(z1, hv.y, w.y);
        w = wn[q];
        fma2(n0, hv.x, w.x); fma2(n1, hv.y, w.y);
    }
}

// shared h1 chunk: 6 rows (layer0 recurrent) + 6 rows (layer1 input proj)
__device__ __forceinline__ void mac12(const ulonglong2* __restrict__ hrow,
    const ulonglong2* __restrict__ wr0, const ulonglong2* __restrict__ wz0,
    const ulonglong2* __restrict__ wn0,
    const ulonglong2* __restrict__ wr1, const ulonglong2* __restrict__ wz1,
    const ulonglong2* __restrict__ wn1,
    ull& r0, ull& r1, ull& z0, ull& z1, ull& n0, ull& n1,
    ull& R0, ull& R1, ull& Z0, ull& Z1, ull& N0, ull& N1) {
#pragma unroll
    for (int q = 0; q < 16; q++) {
        ulonglong2 hv = hrow[q];
        ulonglong2 w  = wr0[q];
        fma2(r0, hv.x, w.x); fma2(r1, hv.y, w.y);
        w = wz0[q];
        fma2(z0, hv.x, w.x); fma2(z1, hv.y, w.y);
        w = wn0[q];
        fma2(n0, hv.x, w.x); fma2(n1, hv.y, w.y);
        w = wr1[q];
        fma2(R0, hv.x, w.x); fma2(R1, hv.y, w.y);
        w = wz1[q];
        fma2(Z0, hv.x, w.x); fma2(Z1, hv.y, w.y);
        w = wn1[q];
        fma2(N0, hv.x, w.x); fma2(N1, hv.y, w.y);
    }
}

__device__ __forceinline__ void stage129(float4* dst, const float* W, int j0, int tid) {
    for (int idx = tid; idx < 12 * 129; idx += NTHREADS) {
        int m = idx / 129, f4 = idx - m * 129;
        int g = m >> 2, u = m & 3;
        float4 v = make_float4(0.f, 0.f, 0.f, 0.f);
        if (f4 < 128)
            v = reinterpret_cast<const float4*>(W + (size_t)(g * HDIM + j0 + u) * HDIM)[f4];
        dst[idx] = v;
    }
}

// ===========  fused 2-layer GRU, software-pipelined by one step  ============
// step s: layer0 computes t=s (s<512), layer1 computes t=s-1 (s>=1).
// Both MAC the SAME staged h1[s-1] tile. Double-buffered tiles, one sync/chunk.
// smem f4 layout: wih0 12x81 | whh0 12x129 | wih1 12x129 | whh1 12x129 | tiles 2x(64x17)
__global__ void __launch_bounds__(NTHREADS, 1)
gru_fused(const int* __restrict__ texts, const float* __restrict__ emb,
          const float* __restrict__ Wih0, const float* __restrict__ Whh0,
          const float* __restrict__ bih0, const float* __restrict__ bhh0,
          const float* __restrict__ Wih1, const float* __restrict__ Whh1,
          const float* __restrict__ bih1, const float* __restrict__ bhh1)
{
    extern __shared__ float4 smem[];
    float4* w_ih0 = smem;                              // 972 f4
    float4* w_hh0 = smem + 972;                        // 1548 f4
    float4* w_ih1 = smem + 972 + 1548;                 // 1548 f4
    float4* w_hh1 = smem + 972 + 2 * 1548;             // 1548 f4
    float4* tiles = smem + 972 + 3 * 1548;             // 2 x 1088 f4
    __shared__ float hn_sh[NTHREADS];
    __shared__ int   tok_sh[BATCH];

    const int tid = threadIdx.x;
    const int j0  = blockIdx.x * 4;
    const int b   = tid >> 2;
    const int jj  = tid & 3;
    const int j   = j0 + jj;

    unsigned ls = *(volatile unsigned*)&g_sense;

    // ---- stage all four weight blocks into SMEM (once) ----
    for (int idx = tid; idx < 972; idx += NTHREADS) {
        int m = idx / 81, f4 = idx - m * 81;
        int g = m >> 2, u = m & 3;
        float4 v = make_float4(0.f, 0.f, 0.f, 0.f);
        if (f4 < 75)
            v = reinterpret_cast<const float4*>(Wih0 + (size_t)(g * HDIM + j0 + u) * EDIM)[f4];
        w_ih0[idx] = v;
    }
    stage129(w_hh0, Whh0, j0, tid);
    stage129(w_ih1, Wih1, j0, tid);
    stage129(w_hh1, Whh1, j0, tid);

    const float br0 = bih0[j] + bhh0[j];
    const float bz0 = bih0[HDIM + j] + bhh0[HDIM + j];
    const float bx0 = bih0[2 * HDIM + j];
    const float bh0 = bhh0[2 * HDIM + j];
    const float br1 = bih1[j] + bhh1[j];
    const float bz1 = bih1[HDIM + j] + bhh1[HDIM + j];
    const float bx1 = bih1[2 * HDIM + j];
    const float bh1 = bhh1[2 * HDIM + j];

    // weight row pointers (16B units; 81/129-f4 padded strides kill bank conflicts)
    const ulonglong2* eR = (const ulonglong2*)(w_ih0 + jj * 81);
    const ulonglong2* eZ = (const ulonglong2*)(w_ih0 + (4 + jj) * 81);
    const ulonglong2* eN = (const ulonglong2*)(w_ih0 + (8 + jj) * 81);
    const ulonglong2* hR0w = (const ulonglong2*)(w_hh0 + jj * 129);
    const ulonglong2* hZ0w = (const ulonglong2*)(w_hh0 + (4 + jj) * 129);
    const ulonglong2* hN0w = (const ulonglong2*)(w_hh0 + (8 + jj) * 129);
    const ulonglong2* xR1w = (const ulonglong2*)(w_ih1 + jj * 129);
    const ulonglong2* xZ1w = (const ulonglong2*)(w_ih1 + (4 + jj) * 129);
    const ulonglong2* xN1w = (const ulonglong2*)(w_ih1 + (8 + jj) * 129);
    const ulonglong2* hR1w = (const ulonglong2*)(w_hh1 + jj * 129);
    const ulonglong2* hZ1w = (const ulonglong2*)(w_hh1 + (4 + jj) * 129);
    const ulonglong2* hN1w = (const ulonglong2*)(w_hh1 + (8 + jj) * 129);

    // per-thread STS destination offsets (fixed across chunks)
    int dof[4];
#pragma unroll
    for (int i = 0; i < 4; i++) {
        int idx = tid + i * NTHREADS;
        dof[i] = (idx >> 4) * 17 + (idx & 15);
    }

// prefetch one chunk's 4 float4 into pr[] (uniform branch: cc same across block)
#define PREFETCH(CC) do { int cc_ = (CC);                                        \
    if (cc_ < cB) {                                                              \
        _Pragma("unroll") for (int i = 0; i < 4; i++) {                          \
            int idx = tid + i * NTHREADS; int rr = idx >> 4, f4 = idx & 15;      \
            int gf4 = cc_ * 16 + f4;                                             \
            float4 v = make_float4(0.f, 0.f, 0.f, 0.f);                          \
            if (gf4 < 75)                                                        \
                v = reinterpret_cast<const float4*>(                             \
                        emb + (size_t)tok_sh[rr] * EDIM)[gf4];                   \
            pr[i] = v; }                                                         \
    } else if (cc_ < cC) { int k = cc_ - cB;                                     \
        _Pragma("unroll") for (int i = 0; i < 4; i++) {                          \
            int idx = tid + i * NTHREADS; int rr = idx >> 4, f4 = idx & 15;      \
            pr[i] = h1p4[rr * 128 + k * 16 + f4]; }                              \
    } else { int k = cc_ - cC;                                                   \
        _Pragma("unroll") for (int i = 0; i < 4; i++) {                          \
            int idx = tid + i * NTHREADS; int rr = idx >> 4, f4 = idx & 15;      \
            pr[i] = h2p4[rr * 128 + k * 16 + f4]; }                              \
    } } while (0)

    for (int s = 0; s <= T_STEPS; s++) {
        const bool do0 = (s < T_STEPS);
        const bool do1 = (s >= 1);
        const float* h1prev = (s == 0) ? g_zero : g_h1 + (size_t)(s - 1) * BH;
        const float* h2prev = (s <= 1) ? g_zero : g_h2 + (size_t)(s - 2) * BH;
        const float4* h1p4 = (const float4*)h1prev;
        const float4* h2p4 = (const float4*)h2prev;
        const int cB = do0 ? 5 : 0;     // emb chunks [0,cB)
        const int cC = cB + 8;          // shared-h1 chunks [cB,cC)
        const int nc = do1 ? cC + 8 : cC;  // h2 chunks [cC,nc)

        if (do0 && tid < BATCH) tok_sh[tid] = texts[s * BATCH + tid];
        __syncthreads();   // tok_sh visible; also closes prev-step hn_sh use

        ull aR0 = 0, aR1 = 0, aZ0 = 0, aZ1 = 0, aX0 = 0, aX1 = 0, aH0 = 0, aH1 = 0;
        ull bR0v = 0, bR1v = 0, bZ0v = 0, bZ1v = 0, bX0v = 0, bX1v = 0, bH0v = 0, bH1v = 0;

        float4 pr[4];
        PREFETCH(0);
        for (int c = 0; c < nc; c++) {
            float4* buf = tiles + (c & 1) * 1088;
#pragma unroll
            for (int i = 0; i < 4; i++) buf[dof[i]] = pr[i];
            __syncthreads();
            if (c + 1 < nc) PREFETCH(c + 1);     // LDG hides behind the MAC below
            const ulonglong2* hrow = (const ulonglong2*)buf + b * 17;
            if (c < cB) {
                mac6(hrow, eR + c * 16, eZ + c * 16, eN + c * 16,
                     aR0, aR1, aZ0, aZ1, aX0, aX1);
            } else if (c < cC) {
                int k = c - cB;
                mac12(hrow, hR0w + k * 16, hZ0w + k * 16, hN0w + k * 16,
                            xR1w + k * 16, xZ1w + k * 16, xN1w + k * 16,
                      aR0, aR1, aZ0, aZ1, aH0, aH1,
                      bR0v, bR1v, bZ0v, bZ1v, bX0v, bX1v);
            } else {
                int k = c - cC;
                mac6(hrow, hR1w + k * 16, hZ1w + k * 16, hN1w + k * 16,
                     bR0v, bR1v, bZ0v, bZ1v, bH0v, bH1v);
            }
        }

        if (do0) {
            float r = sigf(hsum2(aR0) + hsum2(aR1) + br0);
            float z = sigf(hsum2(aZ0) + hsum2(aZ1) + bz0);
            float n = tanhf(hsum2(aX0) + hsum2(aX1) + bx0 +
                            r * (hsum2(aH0) + hsum2(aH1) + bh0));
            float hp = h1prev[b * HDIM + j];
            g_h1[(size_t)s * BH + b * HDIM + j] = (1.0f - z) * n + z * hp;
        }
        if (do1) {
            float r = sigf(hsum2(bR0v) + hsum2(bR1v) + br1);
            float z = sigf(hsum2(bZ0v) + hsum2(bZ1v) + bz1);
            float n = tanhf(hsum2(bX0v) + hsum2(bX1v) + bx1 +
                            r * (hsum2(bH0v) + hsum2(bH1v) + bh1));
            float hp = h2prev[b * HDIM + j];
            float hnew = (1.0f - z) * n + z * hp;
            g_h2[(size_t)(s - 1) * BH + b * HDIM + j] = hnew;

            hn_sh[tid] = hnew;                  // tid = b*4 + jj
            __syncthreads();
            if (tid < 4) {
                float sum = 0.f;
#pragma unroll
                for (int bb = 0; bb < BATCH; bb++) sum += hn_sh[(bb << 2) + tid];
                g_pooled[(s - 1) * HDIM + j0 + tid] = sum * (1.0f / BATCH);
            }
        }

        grid_bar(ls);
    }
#undef PREFETCH
}

// =====================  final FC: [T,H] @ [L,H]^T + b  ======================
__global__ void fc_kernel(const float* __restrict__ fcW, const float* __restrict__ fcb,
                          float* __restrict__ out)
{
    int t    = blockIdx.x;
    int l    = threadIdx.x >> 5;   // 5 warps -> 5 outputs
    int lane = threadIdx.x & 31;
    const float* p = g_pooled + t * HDIM;
    const float* w = fcW + l * HDIM;
    float s = 0.f;
#pragma unroll 4
    for (int k = lane; k < HDIM; k += 32) s += p[k] * w[k];
#pragma unroll
    for (int o = 16; o; o >>= 1) s += __shfl_xor_sync(0xffffffffu, s, o);
    if (lane == 0) out[t * 5 + l] = s + fcb[l];
}

// ===========================================================================
extern "C" void kernel_launch(void* const* d_in, const int* in_sizes, int n_in,
                              void* d_out, int out_size) {
    (void)in_sizes; (void)n_in; (void)out_size;
    const int*   texts = (const int*)  d_in[0];
    const float* emb   = (const float*)d_in[1];
    const float* Wih0  = (const float*)d_in[2];
    const float* Whh0  = (const float*)d_in[3];
    const float* bih0  = (const float*)d_in[4];
    const float* bhh0  = (const float*)d_in[5];
    const float* Wih1  = (const float*)d_in[6];
    const float* Whh1  = (const float*)d_in[7];
    const float* bih1  = (const float*)d_in[8];
    const float* bhh1  = (const float*)d_in[9];
    const float* fcW   = (const float*)d_in[10];
    const float* fcb   = (const float*)d_in[11];
    float* out = (float*)d_out;

    // 972 + 3*1548 + 2*1088 = 7792 float4 = 124,672 B dynamic SMEM
    const int smemB = (972 + 3 * 1548 + 2 * 1088) * 16;
    cudaFuncSetAttribute(gru_fused, cudaFuncAttributeMaxDynamicSharedMemorySize, smemB);

    gru_fused<<<NBLK, NTHREADS, smemB>>>(texts, emb,
                                         Wih0, Whh0, bih0, bhh0,
                                         Wih1, Whh1, bih1, bhh1);
    fc_kernel<<<T_STEPS, 160>>>(fcW, fcb, out);
}

// round 9
// speedup vs baseline: 2.6807x; 1.1952x over previous
#include <cuda_runtime.h>

typedef unsigned long long ull;

#define T_STEPS  512
#define BATCH    64
#define EDIM     300
#define HDIM     512
#define BH       (BATCH * HDIM)
#define NBLK     128
#define NTHREADS 256

// strides in float4 units
#define WIH0_S   82     // 75 real + pad
#define WH_S     130    // 128 real + pad (2-way-conflict-free with kq spread)
#define TILE_S   17     // 16 real + pad

// -------------------- persistent device scratch (no allocations) -----------
__device__ float g_h1[(size_t)T_STEPS * BH];   // layer-0 hidden, all t
__device__ float g_h2[(size_t)T_STEPS * BH];   // layer-1 hidden, all t
__device__ float g_zero[BH];                   // never written: stays 0
__device__ float g_pooled[T_STEPS * HDIM];     // mean over batch of h2
__device__ unsigned g_flags[NBLK];             // all-observe-all barrier flags

// -------------------- helpers ---------------------------------------------
__device__ __forceinline__ void fma2(ull& acc, ull a, ull b) {
    asm volatile("fma.rn.f32x2 %0, %1, %2, %0;" : "+l"(acc) : "l"(a), "l"(b));
}
__device__ __forceinline__ float hsum2(ull v) {
    return __uint_as_float((unsigned)v) + __uint_as_float((unsigned)(v >> 32));
}
__device__ __forceinline__ float sigf(float x) { return 1.0f / (1.0f + expf(-x)); }

// hsum + reduce over the 4 kq lanes (lane bits 0-1)
__device__ __forceinline__ float redq(ull a) {
    float f = hsum2(a);
    f += __shfl_xor_sync(0xffffffffu, f, 1);
    f += __shfl_xor_sync(0xffffffffu, f, 2);
    return f;
}

// ---- register-blocked MAC: 4 batches x 3 rows, 16 K-values (4 f32x4) ------
__device__ __forceinline__ void mac3x4(const ulonglong2* __restrict__ t,
    const ulonglong2* __restrict__ w0, const ulonglong2* __restrict__ w1,
    const ulonglong2* __restrict__ w2,
    ull a0[4], ull a1[4], ull a2[4])
{
#pragma unroll
    for (int i = 0; i < 4; i++) {
        const int o = 4 * i;
        ulonglong2 h0 = t[o], h1 = t[o + 17], h2 = t[o + 34], h3 = t[o + 51];
        ulonglong2 v0 = w0[o], v1 = w1[o], v2 = w2[o];
        fma2(a0[0], h0.x, v0.x); fma2(a0[1], h1.x, v0.x); fma2(a0[2], h2.x, v0.x); fma2(a0[3], h3.x, v0.x);
        fma2(a1[0], h0.x, v1.x); fma2(a1[1], h1.x, v1.x); fma2(a1[2], h2.x, v1.x); fma2(a1[3], h3.x, v1.x);
        fma2(a2[0], h0.x, v2.x); fma2(a2[1], h1.x, v2.x); fma2(a2[2], h2.x, v2.x); fma2(a2[3], h3.x, v2.x);
        fma2(a0[0], h0.y, v0.y); fma2(a0[1], h1.y, v0.y); fma2(a0[2], h2.y, v0.y); fma2(a0[3], h3.y, v0.y);
        fma2(a1[0], h0.y, v1.y); fma2(a1[1], h1.y, v1.y); fma2(a1[2], h2.y, v1.y); fma2(a1[3], h3.y, v1.y);
        fma2(a2[0], h0.y, v2.y); fma2(a2[1], h1.y, v2.y); fma2(a2[2], h2.y, v2.y); fma2(a2[3], h3.y, v2.y);
    }
}

// ---- 4 batches x 6 rows (layer0-recurrent + layer1-input share the tile) --
__device__ __forceinline__ void mac6x4(const ulonglong2* __restrict__ t,
    const ulonglong2* __restrict__ w0, const ulonglong2* __restrict__ w1,
    const ulonglong2* __restrict__ w2, const ulonglong2* __restrict__ w3,
    const ulonglong2* __restrict__ w4, const ulonglong2* __restrict__ w5,
    ull a0[4], ull a1[4], ull a2[4], ull a3[4], ull a4[4], ull a5[4])
{
#pragma unroll
    for (int i = 0; i < 4; i++) {
        const int o = 4 * i;
        ulonglong2 h0 = t[o], h1 = t[o + 17], h2 = t[o + 34], h3 = t[o + 51];
        ulonglong2 v0 = w0[o], v1 = w1[o], v2 = w2[o];
        ulonglong2 v3 = w3[o], v4 = w4[o], v5 = w5[o];
        fma2(a0[0], h0.x, v0.x); fma2(a0[1], h1.x, v0.x); fma2(a0[2], h2.x, v0.x); fma2(a0[3], h3.x, v0.x);
        fma2(a1[0], h0.x, v1.x); fma2(a1[1], h1.x, v1.x); fma2(a1[2], h2.x, v1.x); fma2(a1[3], h3.x, v1.x);
        fma2(a2[0], h0.x, v2.x); fma2(a2[1], h1.x, v2.x); fma2(a2[2], h2.x, v2.x); fma2(a2[3], h3.x, v2.x);
        fma2(a3[0], h0.x, v3.x); fma2(a3[1], h1.x, v3.x); fma2(a3[2], h2.x, v3.x); fma2(a3[3], h3.x, v3.x);
        fma2(a4[0], h0.x, v4.x); fma2(a4[1], h1.x, v4.x); fma2(a4[2], h2.x, v4.x); fma2(a4[3], h3.x, v4.x);
        fma2(a5[0], h0.x, v5.x); fma2(a5[1], h1.x, v5.x); fma2(a5[2], h2.x, v5.x); fma2(a5[3], h3.x, v5.x);
        fma2(a0[0], h0.y, v0.y); fma2(a0[1], h1.y, v0.y); fma2(a0[2], h2.y, v0.y); fma2(a0[3], h3.y, v0.y);
        fma2(a1[0], h0.y, v1.y); fma2(a1[1], h1.y, v1.y); fma2(a1[2], h2.y, v1.y); fma2(a1[3], h3.y, v1.y);
        fma2(a2[0], h0.y, v2.y); fma2(a2[1], h1.y, v2.y); fma2(a2[2], h2.y, v2.y); fma2(a2[3], h3.y, v2.y);
        fma2(a3[0], h0.y, v3.y); fma2(a3[1], h1.y, v3.y); fma2(a3[2], h2.y, v3.y); fma2(a3[3], h3.y, v3.y);
        fma2(a4[0], h0.y, v4.y); fma2(a4[1], h1.y, v4.y); fma2(a4[2], h2.y, v4.y); fma2(a4[3], h3.y, v4.y);
        fma2(a5[0], h0.y, v5.y); fma2(a5[1], h1.y, v5.y); fma2(a5[2], h2.y, v5.y); fma2(a5[3], h3.y, v5.y);
    }
}

__device__ __forceinline__ void stage130(float4* dst, const float* W, int j0, int tid) {
    for (int idx = tid; idx < 12 * WH_S; idx += NTHREADS) {
        int m = idx / WH_S, f4 = idx - m * WH_S;
        int g = m >> 2, u = m & 3;
        float4 v = make_float4(0.f, 0.f, 0.f, 0.f);
        if (f4 < 128)
            v = reinterpret_cast<const float4*>(W + (size_t)(g * HDIM + j0 + u) * HDIM)[f4];
        dst[idx] = v;
    }
}

// ===========  fused 2-layer GRU, register-blocked, flag barrier  ============
// CTA owns units j0..j0+3. Thread = (bg in 16, jj in 4, kq in 4):
//   4 batches (bg*4..+3), unit jj, K-quarter kq (interleaved f4 stride 4).
// step s: layer0 t=s (s<512), layer1 t=s-1 (s>=1); both MAC the h1[s-1] tile.
__global__ void __launch_bounds__(NTHREADS, 1)
gru_fused(const int* __restrict__ texts, const float* __restrict__ emb,
          const float* __restrict__ Wih0, const float* __restrict__ Whh0,
          const float* __restrict__ bih0, const float* __restrict__ bhh0,
          const float* __restrict__ Wih1, const float* __restrict__ Whh1,
          const float* __restrict__ bih1, const float* __restrict__ bhh1)
{
    extern __shared__ float4 smem[];
    float4* w_ih0 = smem;                               // 12*82  = 984 f4
    float4* w_hh0 = smem + 12 * WIH0_S;                 // 12*130 = 1560 f4
    float4* w_ih1 = w_hh0 + 12 * WH_S;
    float4* w_hh1 = w_ih1 + 12 * WH_S;
    float4* tiles = w_hh1 + 12 * WH_S;                  // 2 x 1088 f4
    __shared__ float pool_sh[64];
    __shared__ int   tok_sh[BATCH];

    const int tid = threadIdx.x;
    const int bid = blockIdx.x;
    const int j0  = bid * 4;
    const int bg  = tid >> 4;          // 16 batch-groups (4 batches each)
    const int jj  = (tid >> 2) & 3;    // unit within CTA
    const int kq  = tid & 3;           // K-quarter (lane bits 0-1)
    const int j   = j0 + jj;
    const int b0  = bg * 4;

    const unsigned base = *(volatile unsigned*)&g_flags[bid];

    // ---- stage weights (once) ----
    for (int idx = tid; idx < 12 * WIH0_S; idx += NTHREADS) {
        int m = idx / WIH0_S, f4 = idx - m * WIH0_S;
        int g = m >> 2, u = m & 3;
        float4 v = make_float4(0.f, 0.f, 0.f, 0.f);
        if (f4 < 75)
            v = reinterpret_cast<const float4*>(Wih0 + (size_t)(g * HDIM + j0 + u) * EDIM)[f4];
        w_ih0[idx] = v;
    }
    stage130(w_hh0, Whh0, j0, tid);
    stage130(w_ih1, Wih1, j0, tid);
    stage130(w_hh1, Whh1, j0, tid);

    const float br0 = bih0[j] + bhh0[j];
    const float bz0 = bih0[HDIM + j] + bhh0[HDIM + j];
    const float bx0 = bih0[2 * HDIM + j];
    const float bh0 = bhh0[2 * HDIM + j];
    const float br1 = bih1[j] + bhh1[j];
    const float bz1 = bih1[HDIM + j] + bhh1[HDIM + j];
    const float bx1 = bih1[2 * HDIM + j];
    const float bh1 = bhh1[2 * HDIM + j];

    // per-thread weight row pointers (16B units), offset by kq
    const ulonglong2* eR  = (const ulonglong2*)w_ih0 + (0 + jj) * WIH0_S + kq;
    const ulonglong2* eZ  = (const ulonglong2*)w_ih0 + (4 + jj) * WIH0_S + kq;
    const ulonglong2* eN  = (const ulonglong2*)w_ih0 + (8 + jj) * WIH0_S + kq;
    const ulonglong2* hR0 = (const ulonglong2*)w_hh0 + (0 + jj) * WH_S + kq;
    const ulonglong2* hZ0 = (const ulonglong2*)w_hh0 + (4 + jj) * WH_S + kq;
    const ulonglong2* hN0 = (const ulonglong2*)w_hh0 + (8 + jj) * WH_S + kq;
    const ulonglong2* xR1 = (const ulonglong2*)w_ih1 + (0 + jj) * WH_S + kq;
    const ulonglong2* xZ1 = (const ulonglong2*)w_ih1 + (4 + jj) * WH_S + kq;
    const ulonglong2* xN1 = (const ulonglong2*)w_ih1 + (8 + jj) * WH_S + kq;
    const ulonglong2* hR1 = (const ulonglong2*)w_hh1 + (0 + jj) * WH_S + kq;
    const ulonglong2* hZ1 = (const ulonglong2*)w_hh1 + (4 + jj) * WH_S + kq;
    const ulonglong2* hN1 = (const ulonglong2*)w_hh1 + (8 + jj) * WH_S + kq;

    // per-thread STS destinations (4 float4 per chunk)
    int dof[4];
#pragma unroll
    for (int i = 0; i < 4; i++) {
        int idx = tid + i * NTHREADS;
        dof[i] = (idx >> 4) * TILE_S + (idx & 15);
    }

#define PRE_EMB(CC) do { int c_ = (CC);                                          \
    _Pragma("unroll") for (int i = 0; i < 4; i++) {                              \
        int idx = tid + i * NTHREADS; int rr = idx >> 4, f4 = idx & 15;          \
        int gf4 = c_ * 16 + f4;                                                  \
        float4 v = make_float4(0.f, 0.f, 0.f, 0.f);                              \
        if (gf4 < 75)                                                            \
            v = reinterpret_cast<const float4*>(emb + (size_t)tok_sh[rr] * EDIM)[gf4]; \
        pr[i] = v; } } while (0)
#define PRE_H(SRC, CC) do { int c_ = (CC);                                       \
    _Pragma("unroll") for (int i = 0; i < 4; i++) {                              \
        int idx = tid + i * NTHREADS; int rr = idx >> 4, f4 = idx & 15;          \
        pr[i] = (SRC)[rr * 128 + c_ * 16 + f4]; } } while (0)

    for (int s = 0; s <= T_STEPS; s++) {
        const bool do0 = (s < T_STEPS);
        const bool do1 = (s >= 1);
        const float* h1prev = (s == 0) ? g_zero : g_h1 + (size_t)(s - 1) * BH;
        const float* h2prev = (s <= 1) ? g_zero : g_h2 + (size_t)(s - 2) * BH;
        const float4* h1p4 = (const float4*)h1prev;
        const float4* h2p4 = (const float4*)h2prev;

        if (do0 && tid < BATCH) tok_sh[tid] = texts[s * BATCH + tid];
        __syncthreads();     // tok visible; closes last step's tile/pool use

        ull AR[4] = {0,0,0,0}, AZ[4] = {0,0,0,0}, AX[4] = {0,0,0,0}, AH[4] = {0,0,0,0};
        ull BR[4] = {0,0,0,0}, BZ[4] = {0,0,0,0}, BX[4] = {0,0,0,0}, BHa[4] = {0,0,0,0};

        float4 pr[4];
        int qi = 0;

        // ---- phase A: embedding projection (needs no barrier) ----
        if (do0) {
            PRE_EMB(0);
            for (int c = 0; c < 5; c++) {
                float4* buf = tiles + (qi & 1) * 1088;
#pragma unroll
                for (int i = 0; i < 4; i++) buf[dof[i]] = pr[i];
                __syncthreads();
                if (c < 4) PRE_EMB(c + 1);
                const ulonglong2* tp = (const ulonglong2*)buf + b0 * TILE_S + kq;
                mac3x4(tp, eR + c * 16, eZ + c * 16, eN + c * 16, AR, AZ, AX);
                qi++;
            }
        }

        // ---- grid wait: h1[s-1], h2[s-2] now published by all CTAs ----
        if (tid < NBLK) {
            unsigned tgt = base + (unsigned)s;
            while ((int)(*(volatile unsigned*)&g_flags[tid] - tgt) < 0) { }
        }
        __syncthreads();
        __threadfence();

        // ---- phase B: shared h1[s-1] tile -> layer0-rec + layer1-in ----
        PRE_H(h1p4, 0);
        for (int c = 0; c < 8; c++) {
            float4* buf = tiles + (qi & 1) * 1088;
#pragma unroll
            for (int i = 0; i < 4; i++) buf[dof[i]] = pr[i];
            __syncthreads();
            if (c < 7)       PRE_H(h1p4, c + 1);
            else if (do1)    PRE_H(h2p4, 0);
            const ulonglong2* tp = (const ulonglong2*)buf + b0 * TILE_S + kq;
            mac6x4(tp, hR0 + c * 16, hZ0 + c * 16, hN0 + c * 16,
                       xR1 + c * 16, xZ1 + c * 16, xN1 + c * 16,
                   AR, AZ, AH, BR, BZ, BX);
            qi++;
        }

        // ---- phase C: h2[s-2] tile -> layer1 recurrent ----
        if (do1) {
            for (int c = 0; c < 8; c++) {
                float4* buf = tiles + (qi & 1) * 1088;
#pragma unroll
                for (int i = 0; i < 4; i++) buf[dof[i]] = pr[i];
                __syncthreads();
                if (c < 7) PRE_H(h2p4, c + 1);
                const ulonglong2* tp = (const ulonglong2*)buf + b0 * TILE_S + kq;
                mac3x4(tp, hR1 + c * 16, hZ1 + c * 16, hN1 + c * 16, BR, BZ, BHa);
                qi++;
            }
        }

        // ---- reduce over kq lanes, gate math, stores ----
        float fAR[4], fAZ[4], fAX[4], fAH[4], fBR[4], fBZ[4], fBX[4], fBH[4];
#pragma unroll
        for (int i = 0; i < 4; i++) {
            fAR[i] = redq(AR[i]); fAZ[i] = redq(AZ[i]);
            fAX[i] = redq(AX[i]); fAH[i] = redq(AH[i]);
            fBR[i] = redq(BR[i]); fBZ[i] = redq(BZ[i]);
            fBX[i] = redq(BX[i]); fBH[i] = redq(BHa[i]);
        }

        if (kq == 0) {
            float psum = 0.f;
#pragma unroll
            for (int i = 0; i < 4; i++) {
                int b = b0 + i;
                if (do0) {
                    float r = sigf(fAR[i] + br0);
                    float z = sigf(fAZ[i] + bz0);
                    float n = tanhf(fAX[i] + bx0 + r * (fAH[i] + bh0));
                    float hp = h1prev[b * HDIM + j];
                    g_h1[(size_t)s * BH + b * HDIM + j] = (1.0f - z) * n + z * hp;
                }
                if (do1) {
                    float r = sigf(fBR[i] + br1);
                    float z = sigf(fBZ[i] + bz1);
                    float n = tanhf(fBX[i] + bx1 + r * (fBH[i] + bh1));
                    float hp = h2prev[b * HDIM + j];
                    float hnew = (1.0f - z) * n + z * hp;
                    g_h2[(size_t)(s - 1) * BH + b * HDIM + j] = hnew;
                    psum += hnew;
                }
            }
            pool_sh[tid >> 2] = psum;          // (bg, jj) slot
        }
        __syncthreads();
        if (do1 && tid < 4) {
            float sum = 0.f;
#pragma unroll
            for (int g = 0; g < 16; g++) sum += pool_sh[g * 4 + tid];
            g_pooled[(s - 1) * HDIM + j0 + tid] = sum * (1.0f / BATCH);
        }

        // ---- arrive ----
        __threadfence();
        __syncthreads();
        if (tid == 0)
            *(volatile unsigned*)&g_flags[bid] = base + (unsigned)s + 1u;
    }
#undef PRE_EMB
#undef PRE_H
}

// =====================  final FC: [T,H] @ [L,H]^T + b  ======================
__global__ void fc_kernel(const float* __restrict__ fcW, const float* __restrict__ fcb,
                          float* __restrict__ out)
{
    int t    = blockIdx.x;
    int l    = threadIdx.x >> 5;   // 5 warps -> 5 outputs
    int lane = threadIdx.x & 31;
    const float* p = g_pooled + t * HDIM;
    const float* w = fcW + l * HDIM;
    float s = 0.f;
#pragma unroll 4
    for (int k = lane; k < HDIM; k += 32) s += p[k] * w[k];
#pragma unroll
    for (int o = 16; o; o >>= 1) s += __shfl_xor_sync(0xffffffffu, s, o);
    if (lane == 0) out[t * 5 + l] = s + fcb[l];
}

// ===========================================================================
extern "C" void kernel_launch(void* const* d_in, const int* in_sizes, int n_in,
                              void* d_out, int out_size) {
    (void)in_sizes; (void)n_in; (void)out_size;
    const int*   texts = (const int*)  d_in[0];
    const float* emb   = (const float*)d_in[1];
    const float* Wih0  = (const float*)d_in[2];
    const float* Whh0  = (const float*)d_in[3];
    const float* bih0  = (const float*)d_in[4];
    const float* bhh0  = (const float*)d_in[5];
    const float* Wih1  = (const float*)d_in[6];
    const float* Whh1  = (const float*)d_in[7];
    const float* bih1  = (const float*)d_in[8];
    const float* bhh1  = (const float*)d_in[9];
    const float* fcW   = (const float*)d_in[10];
    const float* fcb   = (const float*)d_in[11];
    float* out = (float*)d_out;

    // 984 + 3*1560 + 2*1088 = 7840 float4 = 125,440 B dynamic SMEM
    const int smemB = (12 * WIH0_S + 3 * 12 * WH_S + 2 * 1088) * 16;
    cudaFuncSetAttribute(gru_fused, cudaFuncAttributeMaxDynamicSharedMemorySize, smemB);

    gru_fused<<<NBLK, NTHREADS, smemB>>>(texts, emb,
                                         Wih0, Whh0, bih0, bhh0,
                                         Wih1, Whh1, bih1, bhh1);
    fc_kernel<<<T_STEPS, 160>>>(fcW, fcb, out);
}